// round 6
// baseline (speedup 1.0000x reference)
#include <cuda_runtime.h>
#include <cuda_bf16.h>
#include <math.h>
#include <stdint.h>

#define TT 2048            // tokens
#define DD 1024            // model dim
#define EE 8               // experts
#define FF 2048            // ffn dim
#define NSLOT (TT*2)       // total (token, expert) rows
#define NW (EE*FF*DD)      // elements per weight tensor

// quantization scales (powers of two -> exact descale)
#define S_ACT 16.f
#define S_WGT 512.f
#define INV_ACC (1.f/8192.f)   // 1/(S_ACT*S_WGT)

// ---------------- scratch (device globals; no allocs allowed) ----------------
__device__ __align__(16) uint8_t g_xn8[TT*DD];
__device__ __align__(16) uint8_t g_w1_8[NW];
__device__ __align__(16) uint8_t g_w2_8[NW];
__device__ __align__(16) uint8_t g_h8[(size_t)NSLOT*FF];
__device__ __align__(16) float g_y[(size_t)NSLOT*DD];
__device__ float g_probs[TT*EE];
__device__ int   g_slot_e[NSLOT];
__device__ float g_slot_w[NSLOT];
__device__ int   g_slot_row[NSLOT];
__device__ int   g_row_tok[NSLOT];
__device__ int   g_n[EE];
__device__ int   g_off[EE];
__device__ int   g_cnt1[EE];

// ================= helpers =================
__device__ __forceinline__ uint32_t smem_u32(const void* p) {
    uint32_t a;
    asm("{ .reg .u64 t; cvta.to.shared.u64 t, %1; cvt.u32.u64 %0, t; }" : "=r"(a) : "l"(p));
    return a;
}
__device__ __forceinline__ void cpa16(uint32_t dst, const void* src) {
    asm volatile("cp.async.cg.shared.global [%0], [%1], 16;" :: "r"(dst), "l"(src) : "memory");
}
#define CP_COMMIT() asm volatile("cp.async.commit_group;" ::: "memory")
#define CP_WAIT2()  asm volatile("cp.async.wait_group 2;" ::: "memory")

__device__ __forceinline__ void ldsm_x4(uint32_t (&r)[4], uint32_t addr) {
    asm volatile("ldmatrix.sync.aligned.m8n8.x4.shared.b16 {%0,%1,%2,%3}, [%4];"
        : "=r"(r[0]), "=r"(r[1]), "=r"(r[2]), "=r"(r[3]) : "r"(addr));
}
__device__ __forceinline__ void mma_fp8(float (&d)[4], const uint32_t (&a)[4],
                                        uint32_t b0, uint32_t b1) {
    asm volatile("mma.sync.aligned.m16n8k32.row.col.f32.e4m3.e4m3.f32 "
        "{%0,%1,%2,%3}, {%4,%5,%6,%7}, {%8,%9}, {%0,%1,%2,%3};"
        : "+f"(d[0]), "+f"(d[1]), "+f"(d[2]), "+f"(d[3])
        : "r"(a[0]), "r"(a[1]), "r"(a[2]), "r"(a[3]), "r"(b0), "r"(b1));
}
__device__ __forceinline__ uint16_t cvt_e4m3x2(float lo, float hi) {
    uint16_t h;
    asm("cvt.rn.satfinite.e4m3x2.f32 %0, %1, %2;" : "=h"(h) : "f"(hi), "f"(lo));
    return h;
}
// smem row = 4 x 16B units + 16B pad (80B); XOR unit swizzle for stores
__device__ __forceinline__ uint32_t rowu_rel(int row, int u) {
    return (uint32_t)row*80u + (uint32_t)((u ^ ((row >> 3) & 3)) * 16);
}

// ---------------- fp32 -> fp8 weight conversion (both tensors, x512) ---------
__global__ void k_cvt8(const float4* __restrict__ w1, const float4* __restrict__ w2,
                       uint2* __restrict__ o1, uint2* __restrict__ o2)
{
    int half = blockIdx.x >> 13;                        // NW/8/256 = 8192 blocks each
    int i = (blockIdx.x & 8191)*256 + threadIdx.x;
    const float4* in = half ? w2 : w1;
    uint2* outp = half ? o2 : o1;
    float4 a = in[2*i], b = in[2*i+1];
    uint32_t u0 = (uint32_t)cvt_e4m3x2(a.x*S_WGT, a.y*S_WGT)
                | ((uint32_t)cvt_e4m3x2(a.z*S_WGT, a.w*S_WGT) << 16);
    uint32_t u1 = (uint32_t)cvt_e4m3x2(b.x*S_WGT, b.y*S_WGT)
                | ((uint32_t)cvt_e4m3x2(b.z*S_WGT, b.w*S_WGT) << 16);
    outp[i] = make_uint2(u0, u1);
}

// ---------------- kernel 1: rmsnorm + router (fp8 xn out) --------------------
__global__ void k_norm_router(const float* __restrict__ x,
                              const float* __restrict__ gw,
                              const float* __restrict__ nw)
{
    int t = blockIdx.x, tid = threadIdx.x;
    __shared__ float red[256];
    __shared__ float r8[8*256];

    const float4* x4 = reinterpret_cast<const float4*>(x) + (size_t)t*256;
    float4 xv = x4[tid];
    float ss = xv.x*xv.x + xv.y*xv.y + xv.z*xv.z + xv.w*xv.w;
    red[tid] = ss; __syncthreads();
    for (int s = 128; s > 0; s >>= 1) {
        if (tid < s) red[tid] += red[tid+s];
        __syncthreads();
    }
    float rstd = rsqrtf(red[0]*(1.0f/1024.0f) + 1.1920928955078125e-07f);

    float4 w = reinterpret_cast<const float4*>(nw)[tid];
    float4 xn;
    xn.x = xv.x*rstd*w.x; xn.y = xv.y*rstd*w.y;
    xn.z = xv.z*rstd*w.z; xn.w = xv.w*rstd*w.w;
    uint32_t pk = (uint32_t)cvt_e4m3x2(xn.x*S_ACT, xn.y*S_ACT)
                | ((uint32_t)cvt_e4m3x2(xn.z*S_ACT, xn.w*S_ACT) << 16);
    reinterpret_cast<uint32_t*>(g_xn8)[(size_t)t*256 + tid] = pk;

    const float4* gw4 = reinterpret_cast<const float4*>(gw);
#pragma unroll
    for (int e = 0; e < 8; e++) {
        float4 g = gw4[e*256 + tid];
        r8[e*256 + tid] = xn.x*g.x + xn.y*g.y + xn.z*g.z + xn.w*g.w;
    }
    __syncthreads();
    for (int s = 128; s > 0; s >>= 1) {
        if (tid < s) {
#pragma unroll
            for (int e = 0; e < 8; e++) r8[e*256+tid] += r8[e*256+tid+s];
        }
        __syncthreads();
    }

    if (tid == 0) {
        float p[8]; float m = -1e30f;
#pragma unroll
        for (int e = 0; e < 8; e++) { p[e] = r8[e*256]; m = fmaxf(m, p[e]); }
        float s = 0.f;
#pragma unroll
        for (int e = 0; e < 8; e++) { p[e] = expf(p[e]-m); s += p[e]; }
        float inv = 1.f/s;
#pragma unroll
        for (int e = 0; e < 8; e++) { p[e] *= inv; g_probs[t*8+e] = p[e]; }
        int e0 = 0;
#pragma unroll
        for (int e = 1; e < 8; e++) if (p[e] > p[e0]) e0 = e;
        int e1 = (e0 == 0) ? 1 : 0;
#pragma unroll
        for (int e = 0; e < 8; e++) if (e != e0 && p[e] > p[e1]) e1 = e;
        float swt = fmaxf(p[e0] + p[e1], 1e-6f);
        g_slot_e[2*t]   = e0; g_slot_e[2*t+1] = e1;
        g_slot_w[2*t]   = p[e0]/swt;
        g_slot_w[2*t+1] = p[e1]/swt;
    }
}

// -------- kernel 2: fused count + offsets + stable placement -----------------
__global__ void k_place()
{
    int e = blockIdx.x, tid = threadIdx.x, lane = tid & 31, w = tid >> 5;
    __shared__ int tot[8];
    __shared__ int c1tot;
    __shared__ int wsum[8];
    __shared__ int chunkbase;

    int c8[8] = {0,0,0,0,0,0,0,0};
    int c1 = 0;
    int se_cache[16];
#pragma unroll
    for (int c = 0; c < 16; c++) {
        int i = c*256 + tid;
        int s = g_slot_e[i];
        se_cache[c] = s;
        c8[s]++;
        if (((i & 1) == 0) && s == e) c1++;
    }
    if (tid < 8) tot[tid] = 0;
    if (tid == 0) c1tot = 0;
    __syncthreads();
#pragma unroll
    for (int k = 0; k < 8; k++) if (c8[k]) atomicAdd(&tot[k], c8[k]);
    if (c1) atomicAdd(&c1tot, c1);
    __syncthreads();

    int base = 0;
#pragma unroll
    for (int k = 0; k < 8; k++) if (k < e) base += tot[k];
    if (tid == 0) {
        g_n[e] = tot[e]; g_off[e] = base; g_cnt1[e] = c1tot;
        chunkbase = base;
    }
    __syncthreads();

#pragma unroll
    for (int c = 0; c < 16; c++) {
        int i = c*256 + tid;
        bool p = (se_cache[c] == e);
        unsigned bal = __ballot_sync(0xffffffffu, p);
        int lp = __popc(bal & ((1u << lane) - 1u));
        if (lane == 0) wsum[w] = __popc(bal);
        __syncthreads();
        int woff = 0;
#pragma unroll
        for (int k = 0; k < 8; k++) if (k < w) woff += wsum[k];
        if (p) {
            int gr = chunkbase + woff + lp;
            g_slot_row[i] = gr;
            g_row_tok[gr] = i >> 1;
        }
        __syncthreads();
        if (tid == 0) {
            int tsum = 0;
#pragma unroll
            for (int k = 0; k < 8; k++) tsum += wsum[k];
            chunkbase += tsum;
        }
        __syncthreads();
    }
}

// ---------------- grouped fp8 tensor-core GEMM (mma.sync e4m3) ---------------
// CTA tile 128x128, K-chunk = 64 B (K=64 fp8). 8 warps = 2x4; warp tile 64x32.
// 4-stage cp.async; 80B padded+swizzled rows; ldsm addrs precomputed; k-loop
// unrolled x4 so stage offsets constant-fold.
template<bool SILU8, bool GATHER>
__global__ void __launch_bounds__(256, 2) gemm_fp8(
    const uint8_t* __restrict__ A,
    const uint8_t* __restrict__ Bw,
    void* __restrict__ Cv,
    int ldaB, int kdB, int ldc, size_t bstrideB)
{
    constexpr uint32_t STG = 256 * 80;       // bytes per stage (A 128 rows + B 128 rows)
    constexpr uint32_t bOff = 128 * 80;

    int e = blockIdx.z;
    int n_e = g_n[e];
    int rowBase = blockIdx.y * 128;
    if (rowBase >= n_e) return;
    int off = g_off[e];
    int colBase = blockIdx.x * 128;

    extern __shared__ char smraw[];
    uint32_t sm0 = smem_u32(smraw);

    int tid = threadIdx.x, wid = tid >> 5, lane = tid & 31;
    int rowWarp = wid & 1, colWarp = wid >> 1;

    // ---- global->smem mapping ----
    int aR = tid >> 1;
    int aS = (tid & 1) * 2;
    const uint8_t* aRow;
    {
        int src;
        if (GATHER) src = (rowBase + aR < n_e) ? g_row_tok[off + rowBase + aR] : 0;
        else { int gr = off + rowBase + aR; src = (gr < NSLOT) ? gr : 0; }
        aRow = A + (size_t)src * ldaB;
    }
    const uint8_t* bRow = Bw + (size_t)e * bstrideB + (size_t)(colBase + aR) * kdB;
    uint32_t aDst0 = sm0 + rowu_rel(aR, aS);
    uint32_t aDst1 = sm0 + rowu_rel(aR, aS + 1);
    uint32_t bDst0 = sm0 + bOff + rowu_rel(aR, aS);
    uint32_t bDst1 = sm0 + bOff + rowu_rel(aR, aS + 1);

    // ---- precomputed ldmatrix relative addresses ----
    int lr = lane & 15, hiU = lane >> 4;
    int nl = (lane & 7) + ((lane & 16) ? 8 : 0);
    int kcU = (lane >> 3) & 1;
    uint32_t aAddr[2][4], bAddr[2][2];
#pragma unroll
    for (int ks = 0; ks < 2; ks++) {
#pragma unroll
        for (int mi = 0; mi < 4; mi++)
            aAddr[ks][mi] = sm0 + rowu_rel(rowWarp*64 + mi*16 + lr, ks*2 + hiU);
#pragma unroll
        for (int nb = 0; nb < 2; nb++)
            bAddr[ks][nb] = sm0 + bOff + rowu_rel(colWarp*32 + nb*16 + nl, ks*2 + kcU);
    }

    float acc[4][4][4];
#pragma unroll
    for (int mi = 0; mi < 4; mi++)
#pragma unroll
        for (int ni = 0; ni < 4; ni++)
#pragma unroll
            for (int j = 0; j < 4; j++) acc[mi][ni][j] = 0.f;

    int nch = kdB >> 6;

#define ISSUE(KB) do { \
    uint32_t _so = (uint32_t)((KB) & 3) * STG; \
    const uint8_t* _as = aRow + (KB)*64 + aS*16; \
    const uint8_t* _bs = bRow + (KB)*64 + aS*16; \
    cpa16(aDst0 + _so, _as); cpa16(aDst1 + _so, _as + 16); \
    cpa16(bDst0 + _so, _bs); cpa16(bDst1 + _so, _bs + 16); \
    CP_COMMIT(); } while (0)

    ISSUE(0); ISSUE(1); ISSUE(2);

#pragma unroll 4
    for (int kb = 0; kb < nch; kb++) {
        CP_WAIT2();
        __syncthreads();
        if (kb + 3 < nch) { ISSUE(kb + 3); } else { CP_COMMIT(); }

        uint32_t so = (uint32_t)(kb & 3) * STG;
#pragma unroll
        for (int ks = 0; ks < 2; ks++) {
            uint32_t af[4][4], bf[2][4];
#pragma unroll
            for (int mi = 0; mi < 4; mi++)
                ldsm_x4(af[mi], aAddr[ks][mi] + so);
#pragma unroll
            for (int nb = 0; nb < 2; nb++)
                ldsm_x4(bf[nb], bAddr[ks][nb] + so);
#pragma unroll
            for (int mi = 0; mi < 4; mi++) {
#pragma unroll
                for (int ni = 0; ni < 4; ni++)
                    mma_fp8(acc[mi][ni], af[mi], bf[ni>>1][(ni&1)*2], bf[ni>>1][(ni&1)*2+1]);
            }
        }
        __syncthreads();
    }
#undef ISSUE

    // ---- epilogue ----
    int g  = lane >> 2;
    int tq = lane & 3;
#pragma unroll
    for (int mi = 0; mi < 4; mi++) {
#pragma unroll
        for (int half = 0; half < 2; half++) {
            int rr = rowBase + rowWarp*64 + mi*16 + half*8 + g;
            if (rr >= n_e) continue;
            size_t rowOff = (size_t)(off + rr) * ldc;
#pragma unroll
            for (int ni = 0; ni < 4; ni++) {
                int c = colBase + colWarp*32 + ni*8 + tq*2;
                float v0 = acc[mi][ni][half*2 + 0] * INV_ACC;
                float v1 = acc[mi][ni][half*2 + 1] * INV_ACC;
                if (SILU8) {
                    v0 = v0 / (1.f + expf(-v0));
                    v1 = v1 / (1.f + expf(-v1));
                    uint16_t hq = cvt_e4m3x2(v0*S_ACT, v1*S_ACT);
                    *reinterpret_cast<uint16_t*>(
                        reinterpret_cast<uint8_t*>(Cv) + rowOff + c) = hq;
                } else {
                    *reinterpret_cast<float2*>(
                        reinterpret_cast<float*>(Cv) + rowOff + c) = make_float2(v0, v1);
                }
            }
        }
    }
}

// ---------------- residual + weighted combine --------------------------------
__global__ void k_combine(const float* __restrict__ x,
                          const float* __restrict__ scale,
                          float* __restrict__ out)
{
    int t = blockIdx.x, q = threadIdx.x;
    float sc = 1.f / (1.f + expf(-scale[0]));
    int   r0 = g_slot_row[2*t],   r1 = g_slot_row[2*t+1];
    float w0 = g_slot_w[2*t],     w1 = g_slot_w[2*t+1];
    const float4* x4 = reinterpret_cast<const float4*>(x);
    const float4* y4 = reinterpret_cast<const float4*>(g_y);
    float4 xv = x4[(size_t)t*256 + q];
    float4 a  = y4[(size_t)r0*256 + q];
    float4 b  = y4[(size_t)r1*256 + q];
    float4 o;
    o.x = xv.x + sc*(w0*a.x + w1*b.x);
    o.y = xv.y + sc*(w0*a.y + w1*b.y);
    o.z = xv.z + sc*(w0*a.z + w1*b.z);
    o.w = xv.w + sc*(w0*a.w + w1*b.w);
    reinterpret_cast<float4*>(out)[(size_t)t*256 + q] = o;
}

// ---------------- load-balance loss -------------------------------------------
__global__ void k_lb(float* __restrict__ out, int out_size)
{
    __shared__ float r8[8*256];
    int tid = threadIdx.x;
    float p[8] = {0.f,0.f,0.f,0.f,0.f,0.f,0.f,0.f};
    for (int t = tid; t < TT; t += 256) {
#pragma unroll
        for (int e = 0; e < 8; e++) p[e] += g_probs[t*8+e];
    }
#pragma unroll
    for (int e = 0; e < 8; e++) r8[e*256+tid] = p[e];
    __syncthreads();
    for (int s = 128; s > 0; s >>= 1) {
        if (tid < s) {
#pragma unroll
            for (int e = 0; e < 8; e++) r8[e*256+tid] += r8[e*256+tid+s];
        }
        __syncthreads();
    }
    if (tid == 0 && out_size > TT*DD) {
        float lb = 0.f;
        for (int e = 0; e < 8; e++) {
            float fe = (float)g_cnt1[e] * (1.f/(float)TT);
            float pm = r8[e*256] * (1.f/(float)TT);
            lb += fe * pm;
        }
        out[(size_t)TT*DD] = 8.f * lb;
    }
}

// ---------------- launch ----------------------------------------------------
extern "C" void kernel_launch(void* const* d_in, const int* in_sizes, int n_in,
                              void* d_out, int out_size)
{
    const float* x     = (const float*)d_in[0];
    const float* gw    = (const float*)d_in[1];
    const float* w1    = (const float*)d_in[2];   // [E, F, D]
    const float* w2    = (const float*)d_in[3];   // [E, D, F]
    const float* nw    = (const float*)d_in[4];
    const float* scale = (const float*)d_in[5];
    float* out = (float*)d_out;

    uint8_t *p_xn8, *p_w1_8, *p_w2_8, *p_h8;
    float *p_y;
    cudaGetSymbolAddress((void**)&p_xn8,  g_xn8);
    cudaGetSymbolAddress((void**)&p_w1_8, g_w1_8);
    cudaGetSymbolAddress((void**)&p_w2_8, g_w2_8);
    cudaGetSymbolAddress((void**)&p_h8,   g_h8);
    cudaGetSymbolAddress((void**)&p_y,    g_y);

    const int DSM = 256 * 80 * 4;   // 81920
    static bool attr_done = false;
    if (!attr_done) {
        cudaFuncSetAttribute((const void*)gemm_fp8<true,  true >,
                             cudaFuncAttributeMaxDynamicSharedMemorySize, DSM);
        cudaFuncSetAttribute((const void*)gemm_fp8<false, false>,
                             cudaFuncAttributeMaxDynamicSharedMemorySize, DSM);
        attr_done = true;
    }

    k_norm_router<<<TT, 256>>>(x, gw, nw);                                   // 1
    k_place<<<EE, 256>>>();                                                  // 2
    k_cvt8<<<2*(NW/8/256), 256>>>((const float4*)w1, (const float4*)w2,
                                  (uint2*)p_w1_8, (uint2*)p_w2_8);           // 3
    // H[gr, f] = silu( xn[tok(gr), :] . w1[e][f, :] ),  K = 1024 bytes
    gemm_fp8<true, true><<<dim3(FF/128, NSLOT/128, EE), 256, DSM>>>(
        p_xn8, p_w1_8, p_h8, DD, DD, FF, (size_t)FF*DD);                     // 4 <- profiled
    // Y[gr, d] = H[gr, :] . w2[e][d, :],  K = 2048 bytes
    gemm_fp8<false, false><<<dim3(DD/128, NSLOT/128, EE), 256, DSM>>>(
        p_h8, p_w2_8, p_y, FF, FF, DD, (size_t)DD*FF);                       // 5
    k_combine<<<TT, 256>>>(x, scale, out);                                   // 6
    k_lb<<<1, 256>>>(out, out_size);                                         // 7
}

// round 7
// speedup vs baseline: 1.1069x; 1.1069x over previous
#include <cuda_runtime.h>
#include <cuda_bf16.h>
#include <cuda_fp16.h>
#include <math.h>
#include <stdint.h>

#define TT 2048            // tokens
#define DD 1024            // model dim
#define EE 8               // experts
#define FF 2048            // ffn dim
#define NSLOT (TT*2)       // total (token, expert) rows
#define NW (EE*FF*DD)      // elements per weight tensor

// quantization scales (powers of two -> exact descale)
#define S_ACT 16.f
#define S_WGT 512.f
#define INV_ACC (1.f/8192.f)   // 1/(S_ACT*S_WGT)

// ---------------- scratch (device globals; no allocs allowed) ----------------
__device__ __align__(16) uint8_t g_xn8[TT*DD];
__device__ __align__(16) uint8_t g_w1_8[NW];
__device__ __align__(16) uint8_t g_w2_8[NW];
__device__ __align__(16) uint8_t g_h8[(size_t)NSLOT*FF];
__device__ __align__(16) float g_y[(size_t)NSLOT*DD];
__device__ float g_probs[TT*EE];
__device__ int   g_slot_e[NSLOT];
__device__ float g_slot_w[NSLOT];
__device__ int   g_slot_row[NSLOT];
__device__ int   g_row_tok[NSLOT];
__device__ int   g_n[EE];
__device__ int   g_off[EE];
__device__ int   g_cnt1[EE];

// ================= helpers =================
__device__ __forceinline__ uint32_t smem_u32(const void* p) {
    uint32_t a;
    asm("{ .reg .u64 t; cvta.to.shared.u64 t, %1; cvt.u32.u64 %0, t; }" : "=r"(a) : "l"(p));
    return a;
}
__device__ __forceinline__ void cpa16(uint32_t dst, const void* src) {
    asm volatile("cp.async.cg.shared.global [%0], [%1], 16;" :: "r"(dst), "l"(src) : "memory");
}
#define CP_COMMIT() asm volatile("cp.async.commit_group;" ::: "memory")
#define CP_WAIT1()  asm volatile("cp.async.wait_group 1;" ::: "memory")

__device__ __forceinline__ void ldsm_x4(uint32_t (&r)[4], uint32_t addr) {
    asm volatile("ldmatrix.sync.aligned.m8n8.x4.shared.b16 {%0,%1,%2,%3}, [%4];"
        : "=r"(r[0]), "=r"(r[1]), "=r"(r[2]), "=r"(r[3]) : "r"(addr));
}
// fp8 e4m3 MMA with f16 accumulator (2 regs = 4 halves)
__device__ __forceinline__ void mma_fp8h(uint32_t (&d)[2], const uint32_t (&a)[4],
                                         uint32_t b0, uint32_t b1) {
    asm volatile("mma.sync.aligned.m16n8k32.row.col.f16.e4m3.e4m3.f16 "
        "{%0,%1}, {%2,%3,%4,%5}, {%6,%7}, {%0,%1};"
        : "+r"(d[0]), "+r"(d[1])
        : "r"(a[0]), "r"(a[1]), "r"(a[2]), "r"(a[3]), "r"(b0), "r"(b1));
}
__device__ __forceinline__ uint16_t cvt_e4m3x2(float lo, float hi) {
    uint16_t h;
    asm("cvt.rn.satfinite.e4m3x2.f32 %0, %1, %2;" : "=h"(h) : "f"(hi), "f"(lo));
    return h;
}
// smem row = 4 x 16B units + 16B pad (80B); XOR unit swizzle for stores
__device__ __forceinline__ uint32_t rowu_rel(int row, int u) {
    return (uint32_t)row*80u + (uint32_t)((u ^ ((row >> 3) & 3)) * 16);
}

// ---------------- fp32 -> fp8 weight conversion (both tensors, x512) ---------
__global__ void k_cvt8(const float4* __restrict__ w1, const float4* __restrict__ w2,
                       uint2* __restrict__ o1, uint2* __restrict__ o2)
{
    int half_ = blockIdx.x >> 13;
    int i = (blockIdx.x & 8191)*256 + threadIdx.x;
    const float4* in = half_ ? w2 : w1;
    uint2* outp = half_ ? o2 : o1;
    float4 a = in[2*i], b = in[2*i+1];
    uint32_t u0 = (uint32_t)cvt_e4m3x2(a.x*S_WGT, a.y*S_WGT)
                | ((uint32_t)cvt_e4m3x2(a.z*S_WGT, a.w*S_WGT) << 16);
    uint32_t u1 = (uint32_t)cvt_e4m3x2(b.x*S_WGT, b.y*S_WGT)
                | ((uint32_t)cvt_e4m3x2(b.z*S_WGT, b.w*S_WGT) << 16);
    outp[i] = make_uint2(u0, u1);
}

// ---------------- kernel 1: rmsnorm + router (fp8 xn out) --------------------
__global__ void k_norm_router(const float* __restrict__ x,
                              const float* __restrict__ gw,
                              const float* __restrict__ nw)
{
    int t = blockIdx.x, tid = threadIdx.x;
    __shared__ float red[256];
    __shared__ float r8[8*256];

    const float4* x4 = reinterpret_cast<const float4*>(x) + (size_t)t*256;
    float4 xv = x4[tid];
    float ss = xv.x*xv.x + xv.y*xv.y + xv.z*xv.z + xv.w*xv.w;
    red[tid] = ss; __syncthreads();
    for (int s = 128; s > 0; s >>= 1) {
        if (tid < s) red[tid] += red[tid+s];
        __syncthreads();
    }
    float rstd = rsqrtf(red[0]*(1.0f/1024.0f) + 1.1920928955078125e-07f);

    float4 w = reinterpret_cast<const float4*>(nw)[tid];
    float4 xn;
    xn.x = xv.x*rstd*w.x; xn.y = xv.y*rstd*w.y;
    xn.z = xv.z*rstd*w.z; xn.w = xv.w*rstd*w.w;
    uint32_t pk = (uint32_t)cvt_e4m3x2(xn.x*S_ACT, xn.y*S_ACT)
                | ((uint32_t)cvt_e4m3x2(xn.z*S_ACT, xn.w*S_ACT) << 16);
    reinterpret_cast<uint32_t*>(g_xn8)[(size_t)t*256 + tid] = pk;

    const float4* gw4 = reinterpret_cast<const float4*>(gw);
#pragma unroll
    for (int e = 0; e < 8; e++) {
        float4 g = gw4[e*256 + tid];
        r8[e*256 + tid] = xn.x*g.x + xn.y*g.y + xn.z*g.z + xn.w*g.w;
    }
    __syncthreads();
    for (int s = 128; s > 0; s >>= 1) {
        if (tid < s) {
#pragma unroll
            for (int e = 0; e < 8; e++) r8[e*256+tid] += r8[e*256+tid+s];
        }
        __syncthreads();
    }

    if (tid == 0) {
        float p[8]; float m = -1e30f;
#pragma unroll
        for (int e = 0; e < 8; e++) { p[e] = r8[e*256]; m = fmaxf(m, p[e]); }
        float s = 0.f;
#pragma unroll
        for (int e = 0; e < 8; e++) { p[e] = expf(p[e]-m); s += p[e]; }
        float inv = 1.f/s;
#pragma unroll
        for (int e = 0; e < 8; e++) { p[e] *= inv; g_probs[t*8+e] = p[e]; }
        int e0 = 0;
#pragma unroll
        for (int e = 1; e < 8; e++) if (p[e] > p[e0]) e0 = e;
        int e1 = (e0 == 0) ? 1 : 0;
#pragma unroll
        for (int e = 0; e < 8; e++) if (e != e0 && p[e] > p[e1]) e1 = e;
        float swt = fmaxf(p[e0] + p[e1], 1e-6f);
        g_slot_e[2*t]   = e0; g_slot_e[2*t+1] = e1;
        g_slot_w[2*t]   = p[e0]/swt;
        g_slot_w[2*t+1] = p[e1]/swt;
    }
}

// -------- kernel 2: count + offsets + stable placement (single block scan) ---
// thread t owns contiguous slots [t*16, t*16+16) -> thread order == slot order
__global__ void k_place()
{
    int e = blockIdx.x, tid = threadIdx.x, lane = tid & 31, w = tid >> 5;
    __shared__ int tot[8];
    __shared__ int c1tot;
    __shared__ int wsum[8];

    int se[16];
    int c8[8] = {0,0,0,0,0,0,0,0};
    int c1 = 0;
    int base_i = tid * 16;
#pragma unroll
    for (int j = 0; j < 16; j++) {
        int s = g_slot_e[base_i + j];
        se[j] = s;
        c8[s]++;
        if ((((base_i + j) & 1) == 0) && s == e) c1++;
    }
    int cnt = c8[e];
    if (tid < 8) tot[tid] = 0;
    if (tid == 0) c1tot = 0;
    __syncthreads();
#pragma unroll
    for (int k = 0; k < 8; k++) if (c8[k]) atomicAdd(&tot[k], c8[k]);
    if (c1) atomicAdd(&c1tot, c1);

    // warp inclusive scan of cnt
    int pre = cnt;
#pragma unroll
    for (int d = 1; d < 32; d <<= 1) {
        int v = __shfl_up_sync(0xffffffffu, pre, d);
        if (lane >= d) pre += v;
    }
    if (lane == 31) wsum[w] = pre;
    __syncthreads();

    int woff = 0;
#pragma unroll
    for (int k = 0; k < 8; k++) if (k < w) woff += wsum[k];
    int excl = woff + pre - cnt;

    int base = 0;
#pragma unroll
    for (int k = 0; k < 8; k++) if (k < e) base += tot[k];
    if (tid == 0) { g_n[e] = tot[e]; g_off[e] = base; g_cnt1[e] = c1tot; }

    int pos = base + excl;
#pragma unroll
    for (int j = 0; j < 16; j++) {
        if (se[j] == e) {
            g_slot_row[base_i + j] = pos;
            g_row_tok[pos] = (base_i + j) >> 1;
            pos++;
        }
    }
}

// ---------------- grouped fp8 tensor-core GEMM, f16 accumulators -------------
// CTA tile 128 x TILE_N, K-chunk = 64 B. 8 warps = 2 row x 4 col bands;
// warp tile 64 x (TILE_N/4). 3-stage cp.async; 80B padded+swizzled rows;
// single barrier per chunk; ring offsets in registers (no div/mod).
template<int TILE_N, bool SILU8, bool GATHER>
__global__ void __launch_bounds__(256, 2) gemm_fp8(
    const uint8_t* __restrict__ A,
    const uint8_t* __restrict__ Bw,
    void* __restrict__ Cv,
    int ldaB, int kdB, int ldc, size_t bstrideB)
{
    constexpr int WT_N = TILE_N / 4;
    constexpr int NI   = WT_N / 8;          // 8-col steps per warp (8 or 4)
    constexpr int NB   = NI / 2;            // 16-row B ldsm blocks (4 or 2)
    constexpr int BSEG = TILE_N / 64;       // B 16B units per thread (4 or 2)
    constexpr uint32_t STG = (uint32_t)(128 + TILE_N) * 80u;
    constexpr uint32_t RING = 3u * STG;
    constexpr uint32_t bOff = 128 * 80;

    int e = blockIdx.z;
    int n_e = g_n[e];
    int rowBase = blockIdx.y * 128;
    if (rowBase >= n_e) return;
    int off = g_off[e];
    int colBase = blockIdx.x * TILE_N;

    extern __shared__ char smraw[];
    uint32_t sm0 = smem_u32(smraw);

    int tid = threadIdx.x, wid = tid >> 5, lane = tid & 31;
    int rowWarp = wid & 1, colWarp = wid >> 1;

    // ---- global->smem mapping ----
    int aR = tid >> 1;
    int aS = (tid & 1) * 2;
    const uint8_t* aRow;
    {
        int src;
        if (GATHER) src = (rowBase + aR < n_e) ? g_row_tok[off + rowBase + aR] : 0;
        else { int gr = off + rowBase + aR; src = (gr < NSLOT) ? gr : 0; }
        aRow = A + (size_t)src * ldaB + aS*16;
    }
    uint32_t aDst0 = sm0 + rowu_rel(aR, aS);
    uint32_t aDst1 = sm0 + rowu_rel(aR, aS + 1);

    int bR = (BSEG == 4) ? tid : (tid >> 1);
    int bS = (BSEG == 4) ? 0 : (tid & 1) * 2;
    const uint8_t* bRow = Bw + (size_t)e * bstrideB + (size_t)(colBase + bR) * kdB + bS*16;
    uint32_t bDst[BSEG];
#pragma unroll
    for (int j = 0; j < BSEG; j++) bDst[j] = sm0 + bOff + rowu_rel(bR, bS + j);

    // ---- precomputed ldmatrix relative addresses ----
    int lr = lane & 15, hiU = lane >> 4;
    int nl = (lane & 7) + ((lane & 16) ? 8 : 0);
    int kcU = (lane >> 3) & 1;
    uint32_t aAddr[2][4], bAddr[2][NB];
#pragma unroll
    for (int ks = 0; ks < 2; ks++) {
#pragma unroll
        for (int mi = 0; mi < 4; mi++)
            aAddr[ks][mi] = sm0 + rowu_rel(rowWarp*64 + mi*16 + lr, ks*2 + hiU);
#pragma unroll
        for (int nb = 0; nb < NB; nb++)
            bAddr[ks][nb] = sm0 + bOff + rowu_rel(colWarp*WT_N + nb*16 + nl, ks*2 + kcU);
    }

    uint32_t acc[4][NI][2];
#pragma unroll
    for (int mi = 0; mi < 4; mi++)
#pragma unroll
        for (int ni = 0; ni < NI; ni++) { acc[mi][ni][0] = 0u; acc[mi][ni][1] = 0u; }

    int nch = kdB >> 6;

#define ISSUE(KB, SO) do { \
    const uint8_t* _as = aRow + (KB)*64; \
    cpa16(aDst0 + (SO), _as); cpa16(aDst1 + (SO), _as + 16); \
    const uint8_t* _bs = bRow + (KB)*64; \
    _Pragma("unroll") \
    for (int _j = 0; _j < BSEG; _j++) cpa16(bDst[_j] + (SO), _bs + _j*16); \
    CP_COMMIT(); } while (0)

    ISSUE(0, 0u); ISSUE(1, STG);

    uint32_t soC = 0, soI = 2u * STG;
    for (int kb = 0; kb < nch; kb++) {
        CP_WAIT1();
        __syncthreads();
        if (kb + 2 < nch) { ISSUE(kb + 2, soI); } else { CP_COMMIT(); }
        soI += STG; if (soI == RING) soI = 0;

#pragma unroll
        for (int ks = 0; ks < 2; ks++) {
            uint32_t af[4][4], bf[NB][4];
#pragma unroll
            for (int mi = 0; mi < 4; mi++)
                ldsm_x4(af[mi], aAddr[ks][mi] + soC);
#pragma unroll
            for (int nb = 0; nb < NB; nb++)
                ldsm_x4(bf[nb], bAddr[ks][nb] + soC);
#pragma unroll
            for (int mi = 0; mi < 4; mi++) {
#pragma unroll
                for (int ni = 0; ni < NI; ni++)
                    mma_fp8h(acc[mi][ni], af[mi], bf[ni>>1][(ni&1)*2], bf[ni>>1][(ni&1)*2+1]);
            }
        }
        soC += STG; if (soC == RING) soC = 0;
    }
#undef ISSUE

    // ---- epilogue: f16 acc -> descale -> (silu+fp8 | fp32) ----
    int g  = lane >> 2;
    int tq = lane & 3;
#pragma unroll
    for (int mi = 0; mi < 4; mi++) {
#pragma unroll
        for (int half_ = 0; half_ < 2; half_++) {
            int rr = rowBase + rowWarp*64 + mi*16 + half_*8 + g;
            if (rr >= n_e) continue;
            size_t rowOff = (size_t)(off + rr) * ldc;
#pragma unroll
            for (int ni = 0; ni < NI; ni++) {
                int c = colBase + colWarp*WT_N + ni*8 + tq*2;
                __half2 hv = *reinterpret_cast<__half2*>(&acc[mi][ni][half_]);
                float2 f = __half22float2(hv);
                float v0 = f.x * INV_ACC;
                float v1 = f.y * INV_ACC;
                if (SILU8) {
                    v0 = v0 / (1.f + expf(-v0));
                    v1 = v1 / (1.f + expf(-v1));
                    uint16_t hq = cvt_e4m3x2(v0*S_ACT, v1*S_ACT);
                    *reinterpret_cast<uint16_t*>(
                        reinterpret_cast<uint8_t*>(Cv) + rowOff + c) = hq;
                } else {
                    *reinterpret_cast<float2*>(
                        reinterpret_cast<float*>(Cv) + rowOff + c) = make_float2(v0, v1);
                }
            }
        }
    }
}

// ---------------- residual + weighted combine (+ lb loss in block 0) ---------
__global__ void k_combine(const float* __restrict__ x,
                          const float* __restrict__ scale,
                          float* __restrict__ out, int out_size)
{
    int t = blockIdx.x, q = threadIdx.x;
    float sc = 1.f / (1.f + expf(-scale[0]));
    int   r0 = g_slot_row[2*t],   r1 = g_slot_row[2*t+1];
    float w0 = g_slot_w[2*t],     w1 = g_slot_w[2*t+1];
    const float4* x4 = reinterpret_cast<const float4*>(x);
    const float4* y4 = reinterpret_cast<const float4*>(g_y);
    float4 xv = x4[(size_t)t*256 + q];
    float4 a  = y4[(size_t)r0*256 + q];
    float4 b  = y4[(size_t)r1*256 + q];
    float4 o;
    o.x = xv.x + sc*(w0*a.x + w1*b.x);
    o.y = xv.y + sc*(w0*a.y + w1*b.y);
    o.z = xv.z + sc*(w0*a.z + w1*b.z);
    o.w = xv.w + sc*(w0*a.w + w1*b.w);
    reinterpret_cast<float4*>(out)[(size_t)t*256 + q] = o;

    // block 0 additionally computes the load-balance loss
    if (t == 0 && out_size > TT*DD) {
        __shared__ float r8[8*256];
        float p[8] = {0.f,0.f,0.f,0.f,0.f,0.f,0.f,0.f};
        for (int tt = q; tt < TT; tt += 256) {
#pragma unroll
            for (int e = 0; e < 8; e++) p[e] += g_probs[tt*8+e];
        }
#pragma unroll
        for (int e = 0; e < 8; e++) r8[e*256+q] = p[e];
        __syncthreads();
        for (int s = 128; s > 0; s >>= 1) {
            if (q < s) {
#pragma unroll
                for (int e = 0; e < 8; e++) r8[e*256+q] += r8[e*256+q+s];
            }
            __syncthreads();
        }
        if (q == 0) {
            float lb = 0.f;
            for (int e = 0; e < 8; e++) {
                float fe = (float)g_cnt1[e] * (1.f/(float)TT);
                float pm = r8[e*256] * (1.f/(float)TT);
                lb += fe * pm;
            }
            out[(size_t)TT*DD] = 8.f * lb;
        }
    }
}

// ---------------- launch ----------------------------------------------------
extern "C" void kernel_launch(void* const* d_in, const int* in_sizes, int n_in,
                              void* d_out, int out_size)
{
    const float* x     = (const float*)d_in[0];
    const float* gw    = (const float*)d_in[1];
    const float* w1    = (const float*)d_in[2];   // [E, F, D]
    const float* w2    = (const float*)d_in[3];   // [E, D, F]
    const float* nw    = (const float*)d_in[4];
    const float* scale = (const float*)d_in[5];
    float* out = (float*)d_out;

    uint8_t *p_xn8, *p_w1_8, *p_w2_8, *p_h8;
    float *p_y;
    cudaGetSymbolAddress((void**)&p_xn8,  g_xn8);
    cudaGetSymbolAddress((void**)&p_w1_8, g_w1_8);
    cudaGetSymbolAddress((void**)&p_w2_8, g_w2_8);
    cudaGetSymbolAddress((void**)&p_h8,   g_h8);
    cudaGetSymbolAddress((void**)&p_y,    g_y);

    const int DSM1 = (128 + 256) * 80 * 3;   // 92160  (TILE_N=256, 3 stages)
    const int DSM2 = (128 + 128) * 80 * 3;   // 61440  (TILE_N=128, 3 stages)
    static bool attr_done = false;
    if (!attr_done) {
        cudaFuncSetAttribute((const void*)gemm_fp8<256, true,  true >,
                             cudaFuncAttributeMaxDynamicSharedMemorySize, DSM1);
        cudaFuncSetAttribute((const void*)gemm_fp8<128, false, false>,
                             cudaFuncAttributeMaxDynamicSharedMemorySize, DSM2);
        attr_done = true;
    }

    k_norm_router<<<TT, 256>>>(x, gw, nw);                                   // 1
    k_place<<<EE, 256>>>();                                                  // 2
    k_cvt8<<<2*(NW/8/256), 256>>>((const float4*)w1, (const float4*)w2,
                                  (uint2*)p_w1_8, (uint2*)p_w2_8);           // 3
    // H[gr, f] = silu( xn[tok(gr), :] . w1[e][f, :] ),  K = 1024 bytes
    gemm_fp8<256, true, true><<<dim3(FF/256, NSLOT/128, EE), 256, DSM1>>>(
        p_xn8, p_w1_8, p_h8, DD, DD, FF, (size_t)FF*DD);                     // 4 <- profiled
    // Y[gr, d] = H[gr, :] . w2[e][d, :],  K = 2048 bytes
    gemm_fp8<128, false, false><<<dim3(DD/128, NSLOT/128, EE), 256, DSM2>>>(
        p_h8, p_w2_8, p_y, FF, FF, DD, (size_t)DD*FF);                       // 5
    k_combine<<<TT, 256>>>(x, scale, out, out_size);                         // 6
}